// round 15
// baseline (speedup 1.0000x reference)
#include <cuda_runtime.h>
#include <math.h>

#define N_LEVELS 16
#define HASHMAP_SIZE 32768
#define HASH_MASK 32767u
#define NPTS 524288
#define P1 2654435761u
#define P2 805459861u
#define MBITS 5                       // morton bits per dim
#define NBUCK (1 << (3 * MBITS))      // 32768 buckets

// Materialized per-level tables: [16][32768] x float2 (4 MB), 16B-aligned.
__device__ __align__(16) float2 g_tables[N_LEVELS * HASHMAP_SIZE];

// Counting-sort scratch
__device__ __align__(16) unsigned g_hist[NBUCK];
__device__ __align__(16) unsigned g_offs[NBUCK];
__device__ unsigned g_total;
__device__ float4   g_sx[NPTS];   // sorted (xn0,xn1,xn2, bit-cast orig index)

struct ResParams { float res[N_LEVELS]; };

// ---------------------------------------------------------------------------
// Morton helpers
// ---------------------------------------------------------------------------
__device__ __forceinline__ unsigned part1by2(unsigned v) {
    v &= 0x3FFu;
    v = (v | (v << 16)) & 0x030000FFu;
    v = (v | (v << 8))  & 0x0300F00Fu;
    v = (v | (v << 4))  & 0x030C30C3u;
    v = (v | (v << 2))  & 0x09249249u;
    return v;
}

__device__ __forceinline__ unsigned morton_code(float xn0, float xn1, float xn2) {
    int cx = min(max((int)(xn0 * 32.0f), 0), 31);
    int cy = min(max((int)(xn1 * 32.0f), 0), 31);
    int cz = min(max((int)(xn2 * 32.0f), 0), 31);
    return part1by2((unsigned)cx)
         | (part1by2((unsigned)cy) << 1)
         | (part1by2((unsigned)cz) << 2);
}

// ---------------------------------------------------------------------------
// Kernel 1 (fused): table build + point histogram. g_hist re-zeroed by
// scan_kernel each replay (module-load zero-init covers the first launch).
// ---------------------------------------------------------------------------
__global__ void __launch_bounds__(256) build_hist_kernel(
    const float* __restrict__ A, const float* __restrict__ B,
    const float* __restrict__ x) {
    int idx = blockIdx.x * blockDim.x + threadIdx.x;   // 0 .. 524287
    if (idx == 0) g_total = 0u;

    int l = idx >> 15;
    float4 a = __ldg(reinterpret_cast<const float4*>(A) + idx);
    const float* b = B + l * 8;
    float f0 = a.x * b[0];
    f0 = fmaf(a.y, b[2], f0);
    f0 = fmaf(a.z, b[4], f0);
    f0 = fmaf(a.w, b[6], f0);
    float f1 = a.x * b[1];
    f1 = fmaf(a.y, b[3], f1);
    f1 = fmaf(a.z, b[5], f1);
    f1 = fmaf(a.w, b[7], f1);
    g_tables[idx] = make_float2(f0, f1);

    float xn0 = (__ldg(&x[3 * idx + 0]) + 1.0f) * 0.5f;
    float xn1 = (__ldg(&x[3 * idx + 1]) + 1.0f) * 0.5f;
    float xn2 = (__ldg(&x[3 * idx + 2]) + 1.0f) * 0.5f;
    atomicAdd(&g_hist[morton_code(xn0, xn1, xn2)], 1u);
}

// ---------------------------------------------------------------------------
// Scan: per-block scan; chunk base via atomicAdd on g_total. Re-zeros g_hist.
// 32 blocks x 256 threads x 4 entries = 32768 buckets.
// ---------------------------------------------------------------------------
__global__ void __launch_bounds__(256) scan_kernel() {
    __shared__ unsigned s[256];
    __shared__ unsigned sbase;
    int t = threadIdx.x;
    int base4 = (blockIdx.x * 1024 + t * 4) >> 2;
    uint4 v = reinterpret_cast<const uint4*>(g_hist)[base4];
    unsigned sum = v.x + v.y + v.z + v.w;
    s[t] = sum;
    __syncthreads();
#pragma unroll
    for (int d = 1; d < 256; d <<= 1) {
        unsigned u = (t >= d) ? s[t - d] : 0u;
        __syncthreads();
        s[t] += u;
        __syncthreads();
    }
    if (t == 255) sbase = atomicAdd(&g_total, s[255]);
    unsigned ex = s[t] - sum;
    __syncthreads();
    unsigned base = sbase + ex;
    uint4 o;
    o.x = base;
    o.y = base + v.x;
    o.z = o.y + v.y;
    o.w = o.z + v.z;
    reinterpret_cast<uint4*>(g_offs)[base4] = o;
    reinterpret_cast<uint4*>(g_hist)[base4] = make_uint4(0u, 0u, 0u, 0u);
}

// ---------------------------------------------------------------------------
// Scatter: 4 points per thread for ILP on the atomic+scattered-store chain.
// ---------------------------------------------------------------------------
__global__ void __launch_bounds__(256) scatter_kernel(const float* __restrict__ x) {
    int t = blockIdx.x * blockDim.x + threadIdx.x;   // 0 .. NPTS/4-1
    const float4* xv = reinterpret_cast<const float4*>(x) + 3 * (size_t)t;
    float4 v0 = __ldg(&xv[0]);
    float4 v1 = __ldg(&xv[1]);
    float4 v2 = __ldg(&xv[2]);
    float px[12] = { v0.x, v0.y, v0.z, v0.w,
                     v1.x, v1.y, v1.z, v1.w,
                     v2.x, v2.y, v2.z, v2.w };
    int n0 = 4 * t;
#pragma unroll
    for (int k = 0; k < 4; k++) {
        float xn0 = (px[3 * k + 0] + 1.0f) * 0.5f;
        float xn1 = (px[3 * k + 1] + 1.0f) * 0.5f;
        float xn2 = (px[3 * k + 2] + 1.0f) * 0.5f;
        unsigned code = morton_code(xn0, xn1, xn2);
        unsigned pos = atomicAdd(&g_offs[code], 1u);
        g_sx[pos] = make_float4(xn0, xn1, xn2, __int_as_float(n0 + k));
    }
}

// ---------------------------------------------------------------------------
// Encode (R12 exact): thread = (sorted slot, half of levels), mixed halves
// within a warp (16 same-level lanes per gather instruction). Even-x path
// uses weight-flip. Default launch bounds (40 regs, ~48 warps/SM) — measured
// sweet spot between occupancy and L1 capacity contention.
// ---------------------------------------------------------------------------
__device__ __forceinline__ float2 lerp2(float2 a, float2 b, float t) {
    return make_float2(fmaf(t, b.x - a.x, a.x),
                       fmaf(t, b.y - a.y, a.y));
}

__global__ void __launch_bounds__(256) encode_kernel(
    float* __restrict__ out, ResParams p) {
    int tid = blockIdx.x * blockDim.x + threadIdx.x;   // 0 .. 2*NPTS-1
    int s    = tid >> 1;
    int half = tid & 1;
    int l0   = half << 3;

    float4 c = g_sx[s];
    int n = __float_as_int(c.w);
    float xn0 = c.x, xn1 = c.y, xn2 = c.z;

    float4* o = reinterpret_cast<float4*>(out + (size_t)n * 32) + (half << 2);
    float2 prev;

#pragma unroll
    for (int k = 0; k < 8; k++) {
        int l = l0 + k;
        float r = p.res[l];
        float fx = xn0 * r, fy = xn1 * r, fz = xn2 * r;
        float flx = floorf(fx), fly = floorf(fy), flz = floorf(fz);
        float wx = fx - flx, wy = fy - fly, wz = fz - flz;
        unsigned ix = (unsigned)flx;
        unsigned iy = (unsigned)fly;
        unsigned iz = (unsigned)flz;

        unsigned hy0 = iy * P1;
        unsigned hy1 = hy0 + P1;
        unsigned hz0 = iz * P2;
        unsigned hz1 = hz0 + P2;
        unsigned r00 = hy0 ^ hz0;
        unsigned r10 = hy1 ^ hz0;
        unsigned r01 = hy0 ^ hz1;
        unsigned r11 = hy1 ^ hz1;

        const float2* tab = g_tables + (l << 15);
        float2 m00, m10, m01, m11;

        if ((ix & 1u) == 0u) {
            const float4* tab4 = reinterpret_cast<const float4*>(tab);
            float wxc = 1.0f - wx;
#define XLERP(RYZ, M)                                                       \
            {                                                               \
                unsigned i0 = (ix ^ (RYZ)) & HASH_MASK;                     \
                float4 q = __ldg(&tab4[i0 >> 1]);                           \
                float wp = (i0 & 1u) ? wxc : wx;                            \
                M = make_float2(fmaf(wp, q.z - q.x, q.x),                   \
                                fmaf(wp, q.w - q.y, q.y));                  \
            }
            XLERP(r00, m00)
            XLERP(r10, m10)
            XLERP(r01, m01)
            XLERP(r11, m11)
#undef XLERP
        } else {
            unsigned x1 = ix + 1u;
            float2 a00 = __ldg(&tab[(ix ^ r00) & HASH_MASK]);
            float2 b00 = __ldg(&tab[(x1 ^ r00) & HASH_MASK]);
            float2 a10 = __ldg(&tab[(ix ^ r10) & HASH_MASK]);
            float2 b10 = __ldg(&tab[(x1 ^ r10) & HASH_MASK]);
            float2 a01 = __ldg(&tab[(ix ^ r01) & HASH_MASK]);
            float2 b01 = __ldg(&tab[(x1 ^ r01) & HASH_MASK]);
            float2 a11 = __ldg(&tab[(ix ^ r11) & HASH_MASK]);
            float2 b11 = __ldg(&tab[(x1 ^ r11) & HASH_MASK]);
            m00 = lerp2(a00, b00, wx);
            m10 = lerp2(a10, b10, wx);
            m01 = lerp2(a01, b01, wx);
            m11 = lerp2(a11, b11, wx);
        }

        float2 mm0 = lerp2(m00, m10, wy);
        float2 mm1 = lerp2(m01, m11, wy);
        float2 rr  = lerp2(mm0, mm1, wz);

        if ((k & 1) == 0) {
            prev = rr;
        } else {
            o[k >> 1] = make_float4(prev.x, prev.y, rr.x, rr.y);
        }
    }
}

// ---------------------------------------------------------------------------
// Launch
// ---------------------------------------------------------------------------
extern "C" void kernel_launch(void* const* d_in, const int* in_sizes, int n_in,
                              void* d_out, int out_size) {
    const float* x = (const float*)d_in[0];        // [524288, 3]
    const float* A = (const float*)d_in[1];        // [16, 32768, 4]
    const float* B = (const float*)d_in[2];        // [16, 4, 2]
    float* out = (float*)d_out;                    // [524288, 32]

    // Replicate numpy's resolution computation bit-exactly.
    ResParams p;
    double b = exp((log(512.0) - log(16.0)) / 15.0);
    for (int l = 0; l < N_LEVELS; l++) {
        double bl;
        if (l == 0)      bl = 1.0;
        else if (l == 1) bl = b;
        else if (l == 2) bl = b * b;
        else             bl = pow(b, (double)l);
        p.res[l] = (float)floor(16.0 * bl);
    }

    build_hist_kernel<<<NPTS / 256, 256>>>(A, B, x);
    scan_kernel<<<NBUCK / 1024, 256>>>();
    scatter_kernel<<<(NPTS / 4) / 256, 256>>>(x);
    encode_kernel<<<(2 * NPTS) / 256, 256>>>(out, p);
}

// round 16
// speedup vs baseline: 1.1885x; 1.1885x over previous
#include <cuda_runtime.h>
#include <math.h>

#define N_LEVELS 16
#define HASHMAP_SIZE 32768
#define HASH_MASK 32767u
#define NPTS 524288
#define P1 2654435761u
#define P2 805459861u
#define MBITS 6                       // morton bits per dim (validated optimum)
#define NBUCK (1 << (3 * MBITS))      // 262144 buckets

// Materialized per-level tables: [16][32768] x float2 (4 MB), 16B-aligned.
__device__ __align__(16) float2 g_tables[N_LEVELS * HASHMAP_SIZE];

// Counting-sort scratch
__device__ __align__(16) unsigned g_hist[NBUCK];
__device__ __align__(16) unsigned g_offs[NBUCK];
__device__ unsigned g_total;
__device__ float4   g_sx[NPTS];   // sorted (xn0,xn1,xn2, bit-cast orig index)

struct ResParams { float res[N_LEVELS]; };

// ---------------------------------------------------------------------------
// Morton helpers
// ---------------------------------------------------------------------------
__device__ __forceinline__ unsigned part1by2(unsigned v) {
    v &= 0x3FFu;
    v = (v | (v << 16)) & 0x030000FFu;
    v = (v | (v << 8))  & 0x0300F00Fu;
    v = (v | (v << 4))  & 0x030C30C3u;
    v = (v | (v << 2))  & 0x09249249u;
    return v;
}

__device__ __forceinline__ unsigned morton_code(float xn0, float xn1, float xn2) {
    int cx = min(max((int)(xn0 * 64.0f), 0), 63);
    int cy = min(max((int)(xn1 * 64.0f), 0), 63);
    int cz = min(max((int)(xn2 * 64.0f), 0), 63);
    return part1by2((unsigned)cx)
         | (part1by2((unsigned)cy) << 1)
         | (part1by2((unsigned)cz) << 2);
}

// ---------------------------------------------------------------------------
// Kernel 1 (fused): table build + point histogram. g_hist re-zeroed by
// scan_kernel each replay (module-load zero-init covers the first launch).
// ---------------------------------------------------------------------------
__global__ void __launch_bounds__(256) build_hist_kernel(
    const float* __restrict__ A, const float* __restrict__ B,
    const float* __restrict__ x) {
    int idx = blockIdx.x * blockDim.x + threadIdx.x;   // 0 .. 524287
    if (idx == 0) g_total = 0u;

    int l = idx >> 15;
    float4 a = __ldg(reinterpret_cast<const float4*>(A) + idx);
    const float* b = B + l * 8;
    float f0 = a.x * b[0];
    f0 = fmaf(a.y, b[2], f0);
    f0 = fmaf(a.z, b[4], f0);
    f0 = fmaf(a.w, b[6], f0);
    float f1 = a.x * b[1];
    f1 = fmaf(a.y, b[3], f1);
    f1 = fmaf(a.z, b[5], f1);
    f1 = fmaf(a.w, b[7], f1);
    g_tables[idx] = make_float2(f0, f1);

    float xn0 = (__ldg(&x[3 * idx + 0]) + 1.0f) * 0.5f;
    float xn1 = (__ldg(&x[3 * idx + 1]) + 1.0f) * 0.5f;
    float xn2 = (__ldg(&x[3 * idx + 2]) + 1.0f) * 0.5f;
    atomicAdd(&g_hist[morton_code(xn0, xn1, xn2)], 1u);
}

// ---------------------------------------------------------------------------
// Scan: per-block scan; chunk base via atomicAdd on g_total. Re-zeros g_hist.
// 256 blocks x 256 threads x 4 entries = 262144 buckets.
// ---------------------------------------------------------------------------
__global__ void __launch_bounds__(256) scan_kernel() {
    __shared__ unsigned s[256];
    __shared__ unsigned sbase;
    int t = threadIdx.x;
    int base4 = (blockIdx.x * 1024 + t * 4) >> 2;
    uint4 v = reinterpret_cast<const uint4*>(g_hist)[base4];
    unsigned sum = v.x + v.y + v.z + v.w;
    s[t] = sum;
    __syncthreads();
#pragma unroll
    for (int d = 1; d < 256; d <<= 1) {
        unsigned u = (t >= d) ? s[t - d] : 0u;
        __syncthreads();
        s[t] += u;
        __syncthreads();
    }
    if (t == 255) sbase = atomicAdd(&g_total, s[255]);
    unsigned ex = s[t] - sum;
    __syncthreads();
    unsigned base = sbase + ex;
    uint4 o;
    o.x = base;
    o.y = base + v.x;
    o.z = o.y + v.y;
    o.w = o.z + v.z;
    reinterpret_cast<uint4*>(g_offs)[base4] = o;
    reinterpret_cast<uint4*>(g_hist)[base4] = make_uint4(0u, 0u, 0u, 0u);
}

// ---------------------------------------------------------------------------
// Scatter: 8 points per thread for deeper MLP on the atomic+scattered-store
// chain (ATOMG ~318 cyc + scattered STG latency overlap 8-wide).
// ---------------------------------------------------------------------------
__global__ void __launch_bounds__(256) scatter_kernel(const float* __restrict__ x) {
    int t = blockIdx.x * blockDim.x + threadIdx.x;   // 0 .. NPTS/8-1
    const float4* xv = reinterpret_cast<const float4*>(x) + 6 * (size_t)t;
    float px[24];
#pragma unroll
    for (int i = 0; i < 6; i++) {
        float4 v = __ldg(&xv[i]);
        px[4 * i + 0] = v.x;
        px[4 * i + 1] = v.y;
        px[4 * i + 2] = v.z;
        px[4 * i + 3] = v.w;
    }
    int n0 = 8 * t;
#pragma unroll
    for (int k = 0; k < 8; k++) {
        float xn0 = (px[3 * k + 0] + 1.0f) * 0.5f;
        float xn1 = (px[3 * k + 1] + 1.0f) * 0.5f;
        float xn2 = (px[3 * k + 2] + 1.0f) * 0.5f;
        unsigned code = morton_code(xn0, xn1, xn2);
        unsigned pos = atomicAdd(&g_offs[code], 1u);
        g_sx[pos] = make_float4(xn0, xn1, xn2, __int_as_float(n0 + k));
    }
}

// ---------------------------------------------------------------------------
// Encode (R12 exact): thread = (sorted slot, half of levels), mixed halves
// within a warp (16 same-level lanes per gather instruction). Even-x path
// uses weight-flip. Default launch bounds (40 regs, ~48 warps/SM) — measured
// sweet spot between occupancy and L1 capacity contention.
// ---------------------------------------------------------------------------
__device__ __forceinline__ float2 lerp2(float2 a, float2 b, float t) {
    return make_float2(fmaf(t, b.x - a.x, a.x),
                       fmaf(t, b.y - a.y, a.y));
}

__global__ void __launch_bounds__(256) encode_kernel(
    float* __restrict__ out, ResParams p) {
    int tid = blockIdx.x * blockDim.x + threadIdx.x;   // 0 .. 2*NPTS-1
    int s    = tid >> 1;
    int half = tid & 1;
    int l0   = half << 3;

    float4 c = g_sx[s];
    int n = __float_as_int(c.w);
    float xn0 = c.x, xn1 = c.y, xn2 = c.z;

    float4* o = reinterpret_cast<float4*>(out + (size_t)n * 32) + (half << 2);
    float2 prev;

#pragma unroll
    for (int k = 0; k < 8; k++) {
        int l = l0 + k;
        float r = p.res[l];
        float fx = xn0 * r, fy = xn1 * r, fz = xn2 * r;
        float flx = floorf(fx), fly = floorf(fy), flz = floorf(fz);
        float wx = fx - flx, wy = fy - fly, wz = fz - flz;
        unsigned ix = (unsigned)flx;
        unsigned iy = (unsigned)fly;
        unsigned iz = (unsigned)flz;

        unsigned hy0 = iy * P1;
        unsigned hy1 = hy0 + P1;
        unsigned hz0 = iz * P2;
        unsigned hz1 = hz0 + P2;
        unsigned r00 = hy0 ^ hz0;
        unsigned r10 = hy1 ^ hz0;
        unsigned r01 = hy0 ^ hz1;
        unsigned r11 = hy1 ^ hz1;

        const float2* tab = g_tables + (l << 15);
        float2 m00, m10, m01, m11;

        if ((ix & 1u) == 0u) {
            const float4* tab4 = reinterpret_cast<const float4*>(tab);
            float wxc = 1.0f - wx;
#define XLERP(RYZ, M)                                                       \
            {                                                               \
                unsigned i0 = (ix ^ (RYZ)) & HASH_MASK;                     \
                float4 q = __ldg(&tab4[i0 >> 1]);                           \
                float wp = (i0 & 1u) ? wxc : wx;                            \
                M = make_float2(fmaf(wp, q.z - q.x, q.x),                   \
                                fmaf(wp, q.w - q.y, q.y));                  \
            }
            XLERP(r00, m00)
            XLERP(r10, m10)
            XLERP(r01, m01)
            XLERP(r11, m11)
#undef XLERP
        } else {
            unsigned x1 = ix + 1u;
            float2 a00 = __ldg(&tab[(ix ^ r00) & HASH_MASK]);
            float2 b00 = __ldg(&tab[(x1 ^ r00) & HASH_MASK]);
            float2 a10 = __ldg(&tab[(ix ^ r10) & HASH_MASK]);
            float2 b10 = __ldg(&tab[(x1 ^ r10) & HASH_MASK]);
            float2 a01 = __ldg(&tab[(ix ^ r01) & HASH_MASK]);
            float2 b01 = __ldg(&tab[(x1 ^ r01) & HASH_MASK]);
            float2 a11 = __ldg(&tab[(ix ^ r11) & HASH_MASK]);
            float2 b11 = __ldg(&tab[(x1 ^ r11) & HASH_MASK]);
            m00 = lerp2(a00, b00, wx);
            m10 = lerp2(a10, b10, wx);
            m01 = lerp2(a01, b01, wx);
            m11 = lerp2(a11, b11, wx);
        }

        float2 mm0 = lerp2(m00, m10, wy);
        float2 mm1 = lerp2(m01, m11, wy);
        float2 rr  = lerp2(mm0, mm1, wz);

        if ((k & 1) == 0) {
            prev = rr;
        } else {
            o[k >> 1] = make_float4(prev.x, prev.y, rr.x, rr.y);
        }
    }
}

// ---------------------------------------------------------------------------
// Launch
// ---------------------------------------------------------------------------
extern "C" void kernel_launch(void* const* d_in, const int* in_sizes, int n_in,
                              void* d_out, int out_size) {
    const float* x = (const float*)d_in[0];        // [524288, 3]
    const float* A = (const float*)d_in[1];        // [16, 32768, 4]
    const float* B = (const float*)d_in[2];        // [16, 4, 2]
    float* out = (float*)d_out;                    // [524288, 32]

    // Replicate numpy's resolution computation bit-exactly.
    ResParams p;
    double b = exp((log(512.0) - log(16.0)) / 15.0);
    for (int l = 0; l < N_LEVELS; l++) {
        double bl;
        if (l == 0)      bl = 1.0;
        else if (l == 1) bl = b;
        else if (l == 2) bl = b * b;
        else             bl = pow(b, (double)l);
        p.res[l] = (float)floor(16.0 * bl);
    }

    build_hist_kernel<<<NPTS / 256, 256>>>(A, B, x);
    scan_kernel<<<NBUCK / 1024, 256>>>();
    scatter_kernel<<<(NPTS / 8) / 256, 256>>>(x);
    encode_kernel<<<(2 * NPTS) / 256, 256>>>(out, p);
}